// round 5
// baseline (speedup 1.0000x reference)
#include <cuda_runtime.h>
#include <cuda_bf16.h>

// Problem constants
#define LSEQ       103
#define RSTRIDE    104                  // padded slab row stride (floats): 16B-aligned rows
#define DP_STRIDE  97                   // d/p smem stride (odd -> conflict-free column reads)
#define DNA_ELEMS  (32 * 4 * LSEQ)      // 13184 floats, contiguous per CTA
#define PROT_ELEMS (8 * 21 * LSEQ)      // 17304 floats, contiguous per group (8 batches)
#define SLAB_FLOATS (8 * 21 * RSTRIDE)  // 17472 floats padded
#define SLAB_BYTES  (SLAB_FLOATS * 4)   // 69888 B dynamic smem

__global__ __launch_bounds__(256, 2)
void ma_block_kernel(const float* __restrict__ dna,
                     const float* __restrict__ prot,
                     const float* __restrict__ w_dna,
                     const float* __restrict__ w_prot,
                     const float* __restrict__ w_lin,
                     const float* __restrict__ b_lin,
                     float* __restrict__ out)
{
    extern __shared__ float s_slab[];          // padded slab: dna block / prot groups
    __shared__ float  s_d[32 * DP_STRIDE];     // relu(conv(dna)) : 32 rows x 96
    __shared__ float  s_p[32 * DP_STRIDE];     // relu(conv(prot)): 32 rows x 96
    __shared__ float  s_wd[32];                // (4,8)
    __shared__ float  s_wp[168];               // (21,8)
    __shared__ float  s_wl[192];               // (2,96)
    __shared__ float  s_bl[2];

    const int tid = threadIdx.x;
    const int u   = blockIdx.x;                // 0..1023

    if (tid < 32)  s_wd[tid] = w_dna[tid];
    if (tid < 168) s_wp[tid] = w_prot[tid];
    if (tid < 192) s_wl[tid] = w_lin[tid];
    if (tid < 2)   s_bl[tid] = b_lin[tid];

    // ---------------- DNA: padded copy-in, then vectorized-window conv ----------------
    {
        const float* src = dna + (size_t)u * DNA_ELEMS;
        // scalar copy with padding; per-iteration const-div addressing (high MLP)
        #pragma unroll 4
        for (int it = 0; it < (DNA_ELEMS + 255) / 256; it++) {
            int e = tid + it * 256;
            if (e < DNA_ELEMS) {
                int r = e / LSEQ;                  // global row 0..127
                int x = e - r * LSEQ;
                s_slab[r * RSTRIDE + x] = src[e];
            }
        }
        __syncthreads();

        // thread: one batch-row, 12 consecutive conv outputs
        const int row = tid >> 3;              // 0..31 (batch)
        const int j0  = (tid & 7) * 12;        // 0,12,...,84

        float acc[12];
        #pragma unroll
        for (int jj = 0; jj < 12; jj++) acc[jj] = 0.f;

        #pragma unroll
        for (int r = 0; r < 4; r++) {
            const float* srow = s_slab + (row * 4 + r) * RSTRIDE + j0;   // 16B aligned
            float win[19];
            const float4* w4 = reinterpret_cast<const float4*>(srow);
            float4 v0 = w4[0], v1 = w4[1], v2 = w4[2], v3 = w4[3];
            win[0]=v0.x; win[1]=v0.y; win[2]=v0.z; win[3]=v0.w;
            win[4]=v1.x; win[5]=v1.y; win[6]=v1.z; win[7]=v1.w;
            win[8]=v2.x; win[9]=v2.y; win[10]=v2.z; win[11]=v2.w;
            win[12]=v3.x; win[13]=v3.y; win[14]=v3.z; win[15]=v3.w;
            win[16]=srow[16]; win[17]=srow[17]; win[18]=srow[18];
            #pragma unroll
            for (int k = 0; k < 8; k++) {
                const float w = s_wd[r * 8 + k];
                #pragma unroll
                for (int jj = 0; jj < 12; jj++)
                    acc[jj] = fmaf(win[jj + k], w, acc[jj]);
            }
        }
        #pragma unroll
        for (int jj = 0; jj < 12; jj++)
            s_d[row * DP_STRIDE + j0 + jj] = fmaxf(acc[jj], 0.f);
    }

    // ---------------- PROT: 4 groups of 8 batches ----------------
    // warp = batch-in-group; lane: rq = lane>>3 (row-quarter), seg = lane&7 (12 cols).
    // rq0 handles rows 0..5, rq k>=1 rows 5k+1..5k+5; partials combined via shuffles.
    {
        const int b    = tid >> 5;             // 0..7 batch in group (== warp)
        const int lane = tid & 31;
        const int rq   = lane >> 3;            // 0..3
        const int seg  = lane & 7;             // 0..7
        const int j0   = seg * 12;
        const int nrows = (rq == 0) ? 6 : 5;
        const int rbase = (rq == 0) ? 0 : (5 * rq + 1);

        for (int g = 0; g < 4; g++) {
            __syncthreads();                   // prior slab readers done
            const float* src = prot + (size_t)u * (32 * 21 * LSEQ) + (size_t)g * PROT_ELEMS;
            #pragma unroll 4
            for (int it = 0; it < (PROT_ELEMS + 255) / 256; it++) {
                int e = tid + it * 256;
                if (e < PROT_ELEMS) {
                    int r = e / LSEQ;              // 0..167
                    int x = e - r * LSEQ;
                    s_slab[r * RSTRIDE + x] = src[e];
                }
            }
            __syncthreads();

            float acc[12];
            #pragma unroll
            for (int jj = 0; jj < 12; jj++) acc[jj] = 0.f;

            #pragma unroll
            for (int i = 0; i < 6; i++) {
                if (i < nrows) {
                    const int r = rbase + i;
                    const float* srow = s_slab + (b * 21 + r) * RSTRIDE + j0;
                    float win[19];
                    const float4* w4 = reinterpret_cast<const float4*>(srow);
                    float4 v0 = w4[0], v1 = w4[1], v2 = w4[2], v3 = w4[3];
                    win[0]=v0.x; win[1]=v0.y; win[2]=v0.z; win[3]=v0.w;
                    win[4]=v1.x; win[5]=v1.y; win[6]=v1.z; win[7]=v1.w;
                    win[8]=v2.x; win[9]=v2.y; win[10]=v2.z; win[11]=v2.w;
                    win[12]=v3.x; win[13]=v3.y; win[14]=v3.z; win[15]=v3.w;
                    win[16]=srow[16]; win[17]=srow[17]; win[18]=srow[18];
                    #pragma unroll
                    for (int k = 0; k < 8; k++) {
                        const float w = s_wp[r * 8 + k];
                        #pragma unroll
                        for (int jj = 0; jj < 12; jj++)
                            acc[jj] = fmaf(win[jj + k], w, acc[jj]);
                    }
                }
            }

            // combine the 4 row-quarter partials (butterfly over lane bits 3,4)
            #pragma unroll
            for (int jj = 0; jj < 12; jj++) {
                acc[jj] += __shfl_xor_sync(0xffffffffu, acc[jj], 8);
                acc[jj] += __shfl_xor_sync(0xffffffffu, acc[jj], 16);
            }
            if (lane < 8) {
                const int prow = (g * 8 + b) * DP_STRIDE + j0;
                #pragma unroll
                for (int jj = 0; jj < 12; jj++)
                    s_p[prow + jj] = fmaxf(acc[jj], 0.f);
            }
        }
    }

    __syncthreads();

    // ---------------- attention + linear ----------------
    // Output b' = 1024*m + u uses sd[b',c,k] = s_d[c][3m+k], sp likewise.
    const int warp = tid >> 5;
    const int lane = tid & 31;

    #pragma unroll 1
    for (int mi = 0; mi < 4; mi++) {
        const int m   = warp * 4 + mi;         // 0..31
        const int col = 3 * m;

        const float q0 = s_p[lane * DP_STRIDE + col + 0];
        const float q1 = s_p[lane * DP_STRIDE + col + 1];
        const float q2 = s_p[lane * DP_STRIDE + col + 2];

        float lg[32];
        #pragma unroll
        for (int k = 0; k < 32; k++) {
            lg[k] = q0 * s_d[k * DP_STRIDE + col + 0]
                  + q1 * s_d[k * DP_STRIDE + col + 1]
                  + q2 * s_d[k * DP_STRIDE + col + 2];
        }
        float mx = lg[0];
        #pragma unroll
        for (int k = 1; k < 32; k++) mx = fmaxf(mx, lg[k]);

        const float scale = 0.5773502691896258f;   // 1/sqrt(3)
        float sum = 0.f;
        #pragma unroll
        for (int k = 0; k < 32; k++) {
            lg[k] = __expf((lg[k] - mx) * scale);
            sum += lg[k];
        }
        const float inv = 1.f / sum;

        float o0 = 0.f, o1 = 0.f, o2 = 0.f;
        #pragma unroll
        for (int k = 0; k < 32; k++) {
            const float w = lg[k];
            o0 = fmaf(w, s_d[k * DP_STRIDE + col + 0], o0);
            o1 = fmaf(w, s_d[k * DP_STRIDE + col + 1], o1);
            o2 = fmaf(w, s_d[k * DP_STRIDE + col + 2], o2);
        }
        o0 *= inv; o1 *= inv; o2 *= inv;

        const int j = lane * 3;
        float p0 = o0 * s_wl[j]      + o1 * s_wl[j + 1]      + o2 * s_wl[j + 2];
        float p1 = o0 * s_wl[96 + j] + o1 * s_wl[96 + j + 1] + o2 * s_wl[96 + j + 2];

        #pragma unroll
        for (int off = 16; off > 0; off >>= 1) {
            p0 += __shfl_xor_sync(0xffffffffu, p0, off);
            p1 += __shfl_xor_sync(0xffffffffu, p1, off);
        }
        if (lane == 0) {
            const int b2 = m * 1024 + u;
            out[b2 * 2 + 0] = p0 + s_bl[0];
            out[b2 * 2 + 1] = p1 + s_bl[1];
        }
    }
}

extern "C" void kernel_launch(void* const* d_in, const int* in_sizes, int n_in,
                              void* d_out, int out_size)
{
    const float* dna    = (const float*)d_in[0];   // (32768,1,4,103)
    const float* prot   = (const float*)d_in[1];   // (32768,1,21,103)
    const float* w_dna  = (const float*)d_in[2];   // (1,1,4,8)
    const float* w_prot = (const float*)d_in[3];   // (1,1,21,8)
    const float* w_lin  = (const float*)d_in[4];   // (2,96)
    const float* b_lin  = (const float*)d_in[5];   // (2,)
    float* out = (float*)d_out;                    // (32768,1,2)

    cudaFuncSetAttribute(ma_block_kernel,
                         cudaFuncAttributeMaxDynamicSharedMemorySize,
                         (int)SLAB_BYTES);

    ma_block_kernel<<<1024, 256, SLAB_BYTES>>>(dna, prot, w_dna, w_prot, w_lin, b_lin, out);
}

// round 7
// speedup vs baseline: 2.1449x; 2.1449x over previous
#include <cuda_runtime.h>
#include <cuda_bf16.h>

// Problem constants
#define LSEQ       103
#define DP_STRIDE  97                   // d/p smem stride (odd -> conflict-free column reads)
#define DNA_ELEMS  (32 * 4 * LSEQ)      // 13184 floats, contiguous per CTA
#define PROT_ELEMS (8 * 21 * LSEQ)      // 17304 floats, contiguous per group (8 batches)
#define DNA_V4     (DNA_ELEMS / 4)      // 3296
#define PROT_V4    (PROT_ELEMS / 4)     // 4326
#define SLAB_BYTES (PROT_V4 * 16)       // 69216 B dynamic smem

__global__ __launch_bounds__(256, 2)
void ma_block_kernel(const float* __restrict__ dna,
                     const float* __restrict__ prot,
                     const float* __restrict__ w_dna,
                     const float* __restrict__ w_prot,
                     const float* __restrict__ w_lin,
                     const float* __restrict__ b_lin,
                     float* __restrict__ out)
{
    extern __shared__ float4 s_slab4[];        // contiguous slab: dna block / prot groups
    __shared__ float  s_d[32 * DP_STRIDE];     // relu(conv(dna)) : 32 rows x 96
    __shared__ float  s_p[32 * DP_STRIDE];     // relu(conv(prot)): 32 rows x 96
    __shared__ float  s_wd[32];                // (4,8)
    __shared__ float  s_wp[168];               // (21,8)
    __shared__ float  s_wl[192];               // (2,96)
    __shared__ float  s_bl[2];

    float* s_slab = reinterpret_cast<float*>(s_slab4);

    const int tid = threadIdx.x;
    const int u   = blockIdx.x;                // 0..1023

    if (tid < 32)  s_wd[tid] = w_dna[tid];
    if (tid < 168) s_wp[tid] = w_prot[tid];
    if (tid < 192) s_wl[tid] = w_lin[tid];
    if (tid < 2)   s_bl[tid] = b_lin[tid];

    // ---------------- DNA: contiguous float4 copy, then conv ----------------
    {
        const float4* src = reinterpret_cast<const float4*>(dna + (size_t)u * DNA_ELEMS);
        #pragma unroll
        for (int i = tid; i < DNA_V4; i += 256)
            s_slab4[i] = src[i];
        __syncthreads();

        // thread: one batch-row, 12 consecutive conv outputs
        const int row = tid >> 3;              // 0..31 (batch)
        const int j0  = (tid & 7) * 12;        // 0,12,...,84

        float acc[12];
        #pragma unroll
        for (int jj = 0; jj < 12; jj++) acc[jj] = 0.f;

        #pragma unroll
        for (int r = 0; r < 4; r++) {
            const float* srow = s_slab + (row * 4 + r) * LSEQ + j0;
            float win[19];
            #pragma unroll
            for (int x = 0; x < 19; x++) win[x] = srow[x];
            #pragma unroll
            for (int k = 0; k < 8; k++) {
                const float w = s_wd[r * 8 + k];
                #pragma unroll
                for (int jj = 0; jj < 12; jj++)
                    acc[jj] = fmaf(win[jj + k], w, acc[jj]);
            }
        }
        #pragma unroll
        for (int jj = 0; jj < 12; jj++)
            s_d[row * DP_STRIDE + j0 + jj] = fmaxf(acc[jj], 0.f);
    }

    // ---------------- PROT: 4 groups of 8 batches ----------------
    // warp = batch-in-group; lane: rq = lane>>3 (row-quarter), seg = lane&7 (12 cols).
    // rq0 handles rows 0..5, rq k>=1 rows 5k+1..5k+5; partials combined via shuffles.
    {
        const int b    = tid >> 5;             // 0..7 batch in group (== warp)
        const int lane = tid & 31;
        const int rq   = lane >> 3;            // 0..3
        const int seg  = lane & 7;             // 0..7
        const int j0   = seg * 12;
        const int nrows = (rq == 0) ? 6 : 5;
        const int rbase = (rq == 0) ? 0 : (5 * rq + 1);

        for (int g = 0; g < 4; g++) {
            __syncthreads();                   // prior slab readers done
            const float4* src = reinterpret_cast<const float4*>(
                prot + (size_t)u * (32 * 21 * LSEQ) + (size_t)g * PROT_ELEMS);
            #pragma unroll
            for (int i = tid; i < PROT_V4; i += 256)
                s_slab4[i] = src[i];
            __syncthreads();

            float acc[12];
            #pragma unroll
            for (int jj = 0; jj < 12; jj++) acc[jj] = 0.f;

            #pragma unroll
            for (int i = 0; i < 6; i++) {
                if (i < nrows) {
                    const int r = rbase + i;
                    const float* srow = s_slab + (b * 21 + r) * LSEQ + j0;
                    float win[19];
                    #pragma unroll
                    for (int x = 0; x < 19; x++) win[x] = srow[x];
                    #pragma unroll
                    for (int k = 0; k < 8; k++) {
                        const float w = s_wp[r * 8 + k];
                        #pragma unroll
                        for (int jj = 0; jj < 12; jj++)
                            acc[jj] = fmaf(win[jj + k], w, acc[jj]);
                    }
                }
            }

            // combine the 4 row-quarter partials (butterfly over lane bits 3,4)
            #pragma unroll
            for (int jj = 0; jj < 12; jj++) {
                acc[jj] += __shfl_xor_sync(0xffffffffu, acc[jj], 8);
                acc[jj] += __shfl_xor_sync(0xffffffffu, acc[jj], 16);
            }
            if (lane < 8) {
                const int prow = (g * 8 + b) * DP_STRIDE + j0;
                #pragma unroll
                for (int jj = 0; jj < 12; jj++)
                    s_p[prow + jj] = fmaxf(acc[jj], 0.f);
            }
        }
    }

    __syncthreads();

    // ---------------- attention + linear ----------------
    // Output b' = 1024*m + u uses sd[b',c,k] = s_d[c][3m+k], sp likewise.
    const int warp = tid >> 5;
    const int lane = tid & 31;

    #pragma unroll 1
    for (int mi = 0; mi < 4; mi++) {
        const int m   = warp * 4 + mi;         // 0..31
        const int col = 3 * m;

        const float q0 = s_p[lane * DP_STRIDE + col + 0];
        const float q1 = s_p[lane * DP_STRIDE + col + 1];
        const float q2 = s_p[lane * DP_STRIDE + col + 2];

        float lg[32];
        #pragma unroll
        for (int k = 0; k < 32; k++) {
            // same address across lanes -> smem broadcast
            lg[k] = q0 * s_d[k * DP_STRIDE + col + 0]
                  + q1 * s_d[k * DP_STRIDE + col + 1]
                  + q2 * s_d[k * DP_STRIDE + col + 2];
        }
        float mx = lg[0];
        #pragma unroll
        for (int k = 1; k < 32; k++) mx = fmaxf(mx, lg[k]);

        const float scale = 0.5773502691896258f;   // 1/sqrt(3)
        float sum = 0.f;
        #pragma unroll
        for (int k = 0; k < 32; k++) {
            lg[k] = __expf((lg[k] - mx) * scale);
            sum += lg[k];
        }
        const float inv = 1.f / sum;

        float o0 = 0.f, o1 = 0.f, o2 = 0.f;
        #pragma unroll
        for (int k = 0; k < 32; k++) {
            const float w = lg[k];
            o0 = fmaf(w, s_d[k * DP_STRIDE + col + 0], o0);
            o1 = fmaf(w, s_d[k * DP_STRIDE + col + 1], o1);
            o2 = fmaf(w, s_d[k * DP_STRIDE + col + 2], o2);
        }
        o0 *= inv; o1 *= inv; o2 *= inv;

        const int j = lane * 3;
        float p0 = o0 * s_wl[j]      + o1 * s_wl[j + 1]      + o2 * s_wl[j + 2];
        float p1 = o0 * s_wl[96 + j] + o1 * s_wl[96 + j + 1] + o2 * s_wl[96 + j + 2];

        #pragma unroll
        for (int off = 16; off > 0; off >>= 1) {
            p0 += __shfl_xor_sync(0xffffffffu, p0, off);
            p1 += __shfl_xor_sync(0xffffffffu, p1, off);
        }
        if (lane == 0) {
            const int b2 = m * 1024 + u;
            out[b2 * 2 + 0] = p0 + s_bl[0];
            out[b2 * 2 + 1] = p1 + s_bl[1];
        }
    }
}

extern "C" void kernel_launch(void* const* d_in, const int* in_sizes, int n_in,
                              void* d_out, int out_size)
{
    const float* dna    = (const float*)d_in[0];   // (32768,1,4,103)
    const float* prot   = (const float*)d_in[1];   // (32768,1,21,103)
    const float* w_dna  = (const float*)d_in[2];   // (1,1,4,8)
    const float* w_prot = (const float*)d_in[3];   // (1,1,21,8)
    const float* w_lin  = (const float*)d_in[4];   // (2,96)
    const float* b_lin  = (const float*)d_in[5];   // (2,)
    float* out = (float*)d_out;                    // (32768,1,2)

    cudaFuncSetAttribute(ma_block_kernel,
                         cudaFuncAttributeMaxDynamicSharedMemorySize,
                         (int)SLAB_BYTES);

    ma_block_kernel<<<1024, 256, SLAB_BYTES>>>(dna, prot, w_dna, w_prot, w_lin, b_lin, out);
}